// round 1
// baseline (speedup 1.0000x reference)
#include <cuda_runtime.h>

// AffineTransformation: B=32, H=W=512, C=1, fp32.
// Inputs (metadata order): d_in[0] = theta [32,6] f32, d_in[1] = image [32,512,512,1] f32.
// Output: [32,512,512,1] f32.

#define BB 32
#define HH 512
#define WW 512

__global__ __launch_bounds__(128, 8)
void affine_sample_kernel(const float* __restrict__ theta,
                          const float* __restrict__ image,
                          float* __restrict__ out)
{
    const int b = blockIdx.z;

    // theta row for this batch (uniform across block -> L1 broadcast)
    const float t0 = __ldg(theta + b * 6 + 0);
    const float t1 = __ldg(theta + b * 6 + 1);
    const float t2 = __ldg(theta + b * 6 + 2);
    const float t3 = __ldg(theta + b * 6 + 3);
    const float t4 = __ldg(theta + b * 6 + 4);
    const float t5 = __ldg(theta + b * 6 + 5);

    const int row  = blockIdx.y * blockDim.y + threadIdx.y;          // 0..511
    const int col0 = (blockIdx.x * blockDim.x + threadIdx.x) * 4;    // 4 px per thread

    const float inv_w = 2.0f / (float)(WW - 1);
    const float inv_h = 2.0f / (float)(HH - 1);
    const float yn = -1.0f + (float)row * inv_h;

    const float* __restrict__ img = image + (size_t)b * HH * WW;

    float4 res;
    float* r = (float*)&res;

    #pragma unroll
    for (int i = 0; i < 4; i++) {
        const int col = col0 + i;
        const float xn = -1.0f + (float)col * inv_w;

        // src = A @ [xn, yn, 1]
        const float sx = t0 * xn + t1 * yn + t2;
        const float sy = t3 * xn + t4 * yn + t5;

        // rescale to pixel coords: srs = (dim-1)/2 * (s + 1)
        const float fx = 0.5f * (float)(WW - 1) * sx + 0.5f * (float)(WW - 1);
        const float fy = 0.5f * (float)(HH - 1) * sy + 0.5f * (float)(HH - 1);

        const float flx = floorf(fx);
        const float fly = floorf(fy);

        // clamped neighbor coordinates (weights computed from CLAMPED coords,
        // matching the reference's clip-then-delta order)
        const float x0 = fminf(fmaxf(flx,        0.0f), (float)(WW - 1));
        const float x1 = fminf(fmaxf(flx + 1.0f, 0.0f), (float)(WW - 1));
        const float y0 = fminf(fmaxf(fly,        0.0f), (float)(HH - 1));
        const float y1 = fminf(fmaxf(fly + 1.0f, 0.0f), (float)(HH - 1));

        const float wx0 = fmaxf(0.0f, 1.0f - fabsf(fx - x0));
        const float wx1 = fmaxf(0.0f, 1.0f - fabsf(fx - x1));
        const float wy0 = fmaxf(0.0f, 1.0f - fabsf(fy - y0));
        const float wy1 = fmaxf(0.0f, 1.0f - fabsf(fy - y1));

        float v = 0.0f;
        // Early-out: if the sample point is out of FOV all weights are 0 -> skip gathers
        if ((wx0 + wx1) > 0.0f && (wy0 + wy1) > 0.0f) {
            const int ix0 = (int)x0;
            const int ix1 = (int)x1;
            const int iy0 = (int)y0;
            const int iy1 = (int)y1;
            const float* r0 = img + (size_t)iy0 * WW;
            const float* r1 = img + (size_t)iy1 * WW;
            v = wy0 * (wx0 * __ldg(r0 + ix0) + wx1 * __ldg(r0 + ix1))
              + wy1 * (wx0 * __ldg(r1 + ix0) + wx1 * __ldg(r1 + ix1));
        }
        r[i] = fminf(fmaxf(v, 0.0f), 1.0f);
    }

    // coalesced float4 store (W=512 -> always 16B aligned)
    *(float4*)(out + ((size_t)b * HH + row) * WW + col0) = res;
}

extern "C" void kernel_launch(void* const* d_in, const int* in_sizes, int n_in,
                              void* d_out, int out_size)
{
    const float* theta = (const float*)d_in[0];
    const float* image = (const float*)d_in[1];
    float* out = (float*)d_out;

    dim3 block(32, 4, 1);                 // 128 threads; covers 128 cols x 4 rows
    dim3 grid(WW / (32 * 4), HH / 4, BB); // (4, 128, 32)
    affine_sample_kernel<<<grid, block>>>(theta, image, out);
}

// round 2
// speedup vs baseline: 1.1905x; 1.1905x over previous
#include <cuda_runtime.h>

// AffineTransformation: B=32, H=W=512, C=1, fp32.
// d_in[0] = theta [32,6] f32, d_in[1] = image [32,512,512,1] f32 -> out same shape.

#define BB 32
#define HH 512
#define WW 512

__global__ __launch_bounds__(128, 8)
void affine_sample_kernel(const float* __restrict__ theta,
                          const float* __restrict__ image,
                          float* __restrict__ out)
{
    const int b = blockIdx.z;

    const float t0 = __ldg(theta + b * 6 + 0);
    const float t1 = __ldg(theta + b * 6 + 1);
    const float t2 = __ldg(theta + b * 6 + 2);
    const float t3 = __ldg(theta + b * 6 + 3);
    const float t4 = __ldg(theta + b * 6 + 4);
    const float t5 = __ldg(theta + b * 6 + 5);

    const int row  = blockIdx.y * blockDim.y + threadIdx.y;          // 0..511
    const int col0 = (blockIdx.x * blockDim.x + threadIdx.x) * 4;    // 4 px/thread

    const float inv_w = 2.0f / (float)(WW - 1);
    const float inv_h = 2.0f / (float)(HH - 1);
    const float yn  = -1.0f + (float)row  * inv_h;
    const float xn0 = -1.0f + (float)col0 * inv_w;

    // Pixel-space sample coords at i=0; note d(fx)/d(col) == t0, d(fy)/d(col) == t3.
    const float fx0 = 0.5f * (float)(WW - 1) * (t0 * xn0 + t1 * yn + t2) + 0.5f * (float)(WW - 1);
    const float fy0 = 0.5f * (float)(HH - 1) * (t3 * xn0 + t4 * yn + t5) + 0.5f * (float)(HH - 1);
    const float fx3 = fmaf(3.0f, t0, fx0);
    const float fy3 = fmaf(3.0f, t3, fy0);

    const float lox = fminf(fx0, fx3), hix = fmaxf(fx0, fx3);
    const float loy = fminf(fy0, fy3), hiy = fmaxf(fy0, fy3);

    float* const op = out + ((size_t)b * HH + row) * WW + col0;

    // (c) whole span has zero coverage -> store zeros, no gathers
    if (hix <= -1.0f || lox >= (float)WW || hiy <= -1.0f || loy >= (float)HH) {
        *(float4*)op = make_float4(0.f, 0.f, 0.f, 0.f);
        return;
    }

    const float* __restrict__ img = image + (size_t)b * HH * WW;

    float4 res;
    float* r = (float*)&res;

    if (lox >= 0.0f && hix < (float)(WW - 1) && loy >= 0.0f && hiy < (float)(HH - 1)) {
        // (a) fully interior: no clamps, trunc == floor, plain bilinear lerp
        #pragma unroll
        for (int i = 0; i < 4; i++) {
            const float fx = fmaf((float)i, t0, fx0);
            const float fy = fmaf((float)i, t3, fy0);
            const int ix = (int)fx;
            const int iy = (int)fy;
            const float ax = fx - (float)ix;
            const float ay = fy - (float)iy;
            const float* p = img + (size_t)iy * WW + ix;
            const float a = __ldg(p);
            const float bb = __ldg(p + 1);
            const float c = __ldg(p + WW);
            const float d = __ldg(p + WW + 1);
            const float h0 = fmaf(ax, bb - a, a);
            const float h1 = fmaf(ax, d - c, c);
            const float v  = fmaf(ay, h1 - h0, h0);
            r[i] = fminf(fmaxf(v, 0.0f), 1.0f);
        }
    } else {
        // (b) border: full reference semantics (clip-then-delta, edge double-count)
        #pragma unroll
        for (int i = 0; i < 4; i++) {
            const float fx = fmaf((float)i, t0, fx0);
            const float fy = fmaf((float)i, t3, fy0);

            const float flx = floorf(fx);
            const float fly = floorf(fy);

            const float x0 = fminf(fmaxf(flx,        0.0f), (float)(WW - 1));
            const float x1 = fminf(fmaxf(flx + 1.0f, 0.0f), (float)(WW - 1));
            const float y0 = fminf(fmaxf(fly,        0.0f), (float)(HH - 1));
            const float y1 = fminf(fmaxf(fly + 1.0f, 0.0f), (float)(HH - 1));

            const float wx0 = fmaxf(0.0f, 1.0f - fabsf(fx - x0));
            const float wx1 = fmaxf(0.0f, 1.0f - fabsf(fx - x1));
            const float wy0 = fmaxf(0.0f, 1.0f - fabsf(fy - y0));
            const float wy1 = fmaxf(0.0f, 1.0f - fabsf(fy - y1));

            float v = 0.0f;
            if ((wx0 + wx1) > 0.0f && (wy0 + wy1) > 0.0f) {
                const int ix0 = (int)x0;
                const int ix1 = (int)x1;
                const int iy0 = (int)y0;
                const int iy1 = (int)y1;
                const float* r0 = img + (size_t)iy0 * WW;
                const float* r1 = img + (size_t)iy1 * WW;
                v = wy0 * (wx0 * __ldg(r0 + ix0) + wx1 * __ldg(r0 + ix1))
                  + wy1 * (wx0 * __ldg(r1 + ix0) + wx1 * __ldg(r1 + ix1));
            }
            r[i] = fminf(fmaxf(v, 0.0f), 1.0f);
        }
    }

    *(float4*)op = res;
}

extern "C" void kernel_launch(void* const* d_in, const int* in_sizes, int n_in,
                              void* d_out, int out_size)
{
    const float* theta = (const float*)d_in[0];
    const float* image = (const float*)d_in[1];
    float* out = (float*)d_out;

    dim3 block(32, 4, 1);                 // 128 threads; 128 cols x 4 rows per block
    dim3 grid(WW / (32 * 4), HH / 4, BB); // (4, 128, 32)
    affine_sample_kernel<<<grid, block>>>(theta, image, out);
}

// round 3
// speedup vs baseline: 1.2146x; 1.0202x over previous
#include <cuda_runtime.h>

// AffineTransformation: B=32, H=W=512, C=1, fp32.
// d_in[0] = theta [32,6] f32, d_in[1] = image [32,512,512,1] f32 -> out same shape.
//
// Layout: each thread owns 4 VERTICALLY adjacent pixels (same col, rows r0..r0+3).
// Warp lanes are consecutive columns -> gather addresses of a warp-LDG span only
// 32*|t0| floats (vs 128*|t0| with horizontal layout) -> ~4x fewer L1 wavefronts.

#define BB 32
#define HH 512
#define WW 512

__global__ __launch_bounds__(128, 8)
void affine_sample_kernel(const float* __restrict__ theta,
                          const float* __restrict__ image,
                          float* __restrict__ out)
{
    const int b = blockIdx.z;

    const float t0 = __ldg(theta + b * 6 + 0);
    const float t1 = __ldg(theta + b * 6 + 1);
    const float t2 = __ldg(theta + b * 6 + 2);
    const float t3 = __ldg(theta + b * 6 + 3);
    const float t4 = __ldg(theta + b * 6 + 4);
    const float t5 = __ldg(theta + b * 6 + 5);

    const int col  = blockIdx.x * 32 + threadIdx.x;                    // 0..511
    const int row0 = (blockIdx.y * blockDim.y + threadIdx.y) * 4;      // 4 rows/thread

    const float inv_w = 2.0f / (float)(WW - 1);
    const float inv_h = 2.0f / (float)(HH - 1);
    const float xn  = -1.0f + (float)col  * inv_w;
    const float yn0 = -1.0f + (float)row0 * inv_h;

    // Pixel-space coords at j=0; per-row derivatives: d(fx)/d(row)=t1, d(fy)/d(row)=t4.
    const float fx0 = 0.5f * (float)(WW - 1) * (t0 * xn + t1 * yn0 + t2) + 0.5f * (float)(WW - 1);
    const float fy0 = 0.5f * (float)(HH - 1) * (t3 * xn + t4 * yn0 + t5) + 0.5f * (float)(HH - 1);
    const float fx3 = fmaf(3.0f, t1, fx0);
    const float fy3 = fmaf(3.0f, t4, fy0);

    const float lox = fminf(fx0, fx3), hix = fmaxf(fx0, fx3);
    const float loy = fminf(fy0, fy3), hiy = fmaxf(fy0, fy3);

    float* const op = out + ((size_t)b * HH + row0) * WW + col;

    // (c) whole 4-row span has zero coverage -> store zeros, no gathers
    if (hix <= -1.0f || lox >= (float)WW || hiy <= -1.0f || loy >= (float)HH) {
        #pragma unroll
        for (int j = 0; j < 4; j++) op[(size_t)j * WW] = 0.0f;
        return;
    }

    const float* __restrict__ img = image + (size_t)b * HH * WW;

    float r[4];

    if (lox >= 0.0f && hix < (float)(WW - 1) && loy >= 0.0f && hiy < (float)(HH - 1)) {
        // (a) fully interior: no clamps, trunc == floor, plain bilinear lerp
        #pragma unroll
        for (int j = 0; j < 4; j++) {
            const float fx = fmaf((float)j, t1, fx0);
            const float fy = fmaf((float)j, t4, fy0);
            const int ix = (int)fx;
            const int iy = (int)fy;
            const float ax = fx - (float)ix;
            const float ay = fy - (float)iy;
            const float* p = img + (size_t)iy * WW + ix;
            const float a  = __ldg(p);
            const float bb = __ldg(p + 1);
            const float c  = __ldg(p + WW);
            const float d  = __ldg(p + WW + 1);
            const float h0 = fmaf(ax, bb - a, a);
            const float h1 = fmaf(ax, d - c, c);
            const float v  = fmaf(ay, h1 - h0, h0);
            r[j] = fminf(fmaxf(v, 0.0f), 1.0f);
        }
    } else {
        // (b) border: full reference semantics (clip-then-delta, edge double-count)
        #pragma unroll
        for (int j = 0; j < 4; j++) {
            const float fx = fmaf((float)j, t1, fx0);
            const float fy = fmaf((float)j, t4, fy0);

            const float flx = floorf(fx);
            const float fly = floorf(fy);

            const float x0 = fminf(fmaxf(flx,        0.0f), (float)(WW - 1));
            const float x1 = fminf(fmaxf(flx + 1.0f, 0.0f), (float)(WW - 1));
            const float y0 = fminf(fmaxf(fly,        0.0f), (float)(HH - 1));
            const float y1 = fminf(fmaxf(fly + 1.0f, 0.0f), (float)(HH - 1));

            const float wx0 = fmaxf(0.0f, 1.0f - fabsf(fx - x0));
            const float wx1 = fmaxf(0.0f, 1.0f - fabsf(fx - x1));
            const float wy0 = fmaxf(0.0f, 1.0f - fabsf(fy - y0));
            const float wy1 = fmaxf(0.0f, 1.0f - fabsf(fy - y1));

            float v = 0.0f;
            if ((wx0 + wx1) > 0.0f && (wy0 + wy1) > 0.0f) {
                const int ix0 = (int)x0;
                const int ix1 = (int)x1;
                const int iy0 = (int)y0;
                const int iy1 = (int)y1;
                const float* r0p = img + (size_t)iy0 * WW;
                const float* r1p = img + (size_t)iy1 * WW;
                v = wy0 * (wx0 * __ldg(r0p + ix0) + wx1 * __ldg(r0p + ix1))
                  + wy1 * (wx0 * __ldg(r1p + ix0) + wx1 * __ldg(r1p + ix1));
            }
            r[j] = fminf(fmaxf(v, 0.0f), 1.0f);
        }
    }

    // coalesced stores: warp lanes are consecutive cols -> 128B per warp-store
    #pragma unroll
    for (int j = 0; j < 4; j++) op[(size_t)j * WW] = r[j];
}

extern "C" void kernel_launch(void* const* d_in, const int* in_sizes, int n_in,
                              void* d_out, int out_size)
{
    const float* theta = (const float*)d_in[0];
    const float* image = (const float*)d_in[1];
    float* out = (float*)d_out;

    dim3 block(32, 4, 1);                  // 128 threads; tile = 32 cols x 16 rows
    dim3 grid(WW / 32, HH / 16, BB);       // (16, 32, 32) = 16384 blocks
    affine_sample_kernel<<<grid, block>>>(theta, image, out);
}

// round 4
// speedup vs baseline: 1.3170x; 1.0843x over previous
#include <cuda_runtime.h>

// AffineTransformation: B=32, H=W=512, C=1, fp32.
// d_in[0] = theta [32,6] f32, d_in[1] = image [32,512,512,1] f32 -> out same shape.
//
// Thread owns 4 vertically adjacent pixels (same col). Warp lanes = consecutive
// cols -> coalesced stores, compact gather footprint. All addressing is 32-bit.
// Interior fast path issues all 16 gathers before any math (MLP=16).

#define BB 32
#define HH 512
#define WW 512

__global__ __launch_bounds__(128, 10)
void affine_sample_kernel(const float* __restrict__ theta,
                          const float* __restrict__ image,
                          float* __restrict__ out)
{
    const int b = blockIdx.z;

    const float t0 = __ldg(theta + b * 6 + 0);
    const float t1 = __ldg(theta + b * 6 + 1);
    const float t2 = __ldg(theta + b * 6 + 2);
    const float t3 = __ldg(theta + b * 6 + 3);
    const float t4 = __ldg(theta + b * 6 + 4);
    const float t5 = __ldg(theta + b * 6 + 5);

    const int col  = blockIdx.x * 32 + threadIdx.x;                 // 0..511
    const int row0 = (blockIdx.y * blockDim.y + threadIdx.y) * 4;   // 4 rows/thread

    const float inv_w = 2.0f / (float)(WW - 1);
    const float inv_h = 2.0f / (float)(HH - 1);
    const float xn  = -1.0f + (float)col  * inv_w;
    const float yn0 = -1.0f + (float)row0 * inv_h;

    // Pixel-space coords at j=0; per-row derivatives: d(fx)/d(row)=t1, d(fy)/d(row)=t4.
    const float fx0 = 0.5f * (float)(WW - 1) * (t0 * xn + t1 * yn0 + t2) + 0.5f * (float)(WW - 1);
    const float fy0 = 0.5f * (float)(HH - 1) * (t3 * xn + t4 * yn0 + t5) + 0.5f * (float)(HH - 1);
    const float fx3 = fmaf(3.0f, t1, fx0);
    const float fy3 = fmaf(3.0f, t4, fy0);

    const float lox = fminf(fx0, fx3), hix = fmaxf(fx0, fx3);
    const float loy = fminf(fy0, fy3), hiy = fmaxf(fy0, fy3);

    const int obase = (b * HH + row0) * WW + col;   // fits in int32

    // (c) whole 4-row span has zero coverage -> store zeros, no gathers
    if (hix <= -1.0f || lox >= (float)WW || hiy <= -1.0f || loy >= (float)HH) {
        #pragma unroll
        for (int j = 0; j < 4; j++) out[obase + j * WW] = 0.0f;
        return;
    }

    const float* __restrict__ img = image + b * (HH * WW);

    float r[4];

    if (lox >= 0.0f && hix < (float)(WW - 1) && loy >= 0.0f && hiy < (float)(HH - 1)) {
        // (a) fully interior: no clamps, trunc == floor, plain bilinear lerp.
        // Phase 1: addresses + fractions. Phase 2: all 16 LDGs. Phase 3: math.
        float ax[4], ay[4];
        int   base[4];
        #pragma unroll
        for (int j = 0; j < 4; j++) {
            const float fx = fmaf((float)j, t1, fx0);
            const float fy = fmaf((float)j, t4, fy0);
            const int ix = (int)fx;
            const int iy = (int)fy;
            ax[j] = fx - (float)ix;
            ay[j] = fy - (float)iy;
            base[j] = iy * WW + ix;
        }
        float va[4], vb[4], vc[4], vd[4];
        #pragma unroll
        for (int j = 0; j < 4; j++) {
            va[j] = __ldg(img + base[j]);
            vb[j] = __ldg(img + base[j] + 1);
            vc[j] = __ldg(img + base[j] + WW);
            vd[j] = __ldg(img + base[j] + WW + 1);
        }
        #pragma unroll
        for (int j = 0; j < 4; j++) {
            const float h0 = fmaf(ax[j], vb[j] - va[j], va[j]);
            const float h1 = fmaf(ax[j], vd[j] - vc[j], vc[j]);
            r[j] = __saturatef(fmaf(ay[j], h1 - h0, h0));
        }
    } else {
        // (b) border: full reference semantics (clip-then-delta, edge double-count)
        #pragma unroll
        for (int j = 0; j < 4; j++) {
            const float fx = fmaf((float)j, t1, fx0);
            const float fy = fmaf((float)j, t4, fy0);

            const float flx = floorf(fx);
            const float fly = floorf(fy);

            const float x0 = fminf(fmaxf(flx,        0.0f), (float)(WW - 1));
            const float x1 = fminf(fmaxf(flx + 1.0f, 0.0f), (float)(WW - 1));
            const float y0 = fminf(fmaxf(fly,        0.0f), (float)(HH - 1));
            const float y1 = fminf(fmaxf(fly + 1.0f, 0.0f), (float)(HH - 1));

            const float wx0 = fmaxf(0.0f, 1.0f - fabsf(fx - x0));
            const float wx1 = fmaxf(0.0f, 1.0f - fabsf(fx - x1));
            const float wy0 = fmaxf(0.0f, 1.0f - fabsf(fy - y0));
            const float wy1 = fmaxf(0.0f, 1.0f - fabsf(fy - y1));

            float v = 0.0f;
            if ((wx0 + wx1) > 0.0f && (wy0 + wy1) > 0.0f) {
                const int ix0 = (int)x0;
                const int ix1 = (int)x1;
                const int r0o = (int)y0 * WW;
                const int r1o = (int)y1 * WW;
                v = wy0 * (wx0 * __ldg(img + r0o + ix0) + wx1 * __ldg(img + r0o + ix1))
                  + wy1 * (wx0 * __ldg(img + r1o + ix0) + wx1 * __ldg(img + r1o + ix1));
            }
            r[j] = __saturatef(v);
        }
    }

    #pragma unroll
    for (int j = 0; j < 4; j++) out[obase + j * WW] = r[j];
}

extern "C" void kernel_launch(void* const* d_in, const int* in_sizes, int n_in,
                              void* d_out, int out_size)
{
    const float* theta = (const float*)d_in[0];
    const float* image = (const float*)d_in[1];
    float* out = (float*)d_out;

    dim3 block(32, 4, 1);                  // 128 threads; tile = 32 cols x 16 rows
    dim3 grid(WW / 32, HH / 16, BB);       // (16, 32, 32) = 16384 blocks
    affine_sample_kernel<<<grid, block>>>(theta, image, out);
}